// round 14
// baseline (speedup 1.0000x reference)
#include <cuda_runtime.h>
#include <cuda_fp16.h>
#include <mma.h>
#include <cstdint>

using namespace nvcuda;

#define T_ 4
#define B_ 16
#define C_ 256
#define N_ 1024
#define CN_ (C_*N_)          // 262144
#define BCN (B_*C_*N_)       // 4194304
#define TBCN (T_*BCN)        // 16777216
#define BHN (B_*8*N_)        // 131072
#define NBITS (T_*BHN)       // 524288 words per branch

// Scratch (device globals: allocation-free)
__device__ float    g_y[3][TBCN];     // post-BN pre-LIF activations for q,k,v
__device__ unsigned g_bits[4][NBITS]; // spike bitpacks: q,k,v, xs
__device__ float    g_kvm[T_*B_*8*1024]; // kv matrices: [t,b,h][32 d][32 e]
__device__ float    g_wt[C_*C_];      // p_w transposed
__device__ __align__(16) __half g_wsplit[3][2][C_*C_]; // fp16 2-term split of q/k/v W
__device__ __align__(16) __half g_xsplit[2][TBCN];     // fp16 2-term split of X

__device__ __forceinline__ uint32_t smem_u32(const void* p) {
    return (uint32_t)__cvta_generic_to_shared(p);
}
__device__ __forceinline__ void cp_async16(uint32_t saddr, const void* g) {
    asm volatile("cp.async.ca.shared.global [%0], [%1], 16;" :: "r"(saddr), "l"(g));
}

// ===========================================================================
// One-shot: 2-term fp16 split of q/k/v weights
// ===========================================================================
__global__ __launch_bounds__(256)
void wsplit_kernel(const float* __restrict__ qw, const float* __restrict__ kw,
                   const float* __restrict__ vw)
{
    int idx = blockIdx.x * 256 + threadIdx.x;         // < 3*65536
    int proj = idx >> 16, e = idx & 65535;
    const float* W = proj == 0 ? qw : (proj == 1 ? kw : vw);
    float x = W[e];
    __half h1 = __float2half_rn(x);
    __half h2 = __float2half_rn(x - __half2float(h1));
    g_wsplit[proj][0][e] = h1;
    g_wsplit[proj][1][e] = h2;
}

// ===========================================================================
// 2-term fp16 split of X (same values as the old in-kernel convert).
// float4 in -> 2x uint2 (4 fp16) out per term; fully coalesced.
// ===========================================================================
__global__ __launch_bounds__(256)
void xsplit_kernel(const float* __restrict__ X)
{
    int idx = blockIdx.x * 256 + threadIdx.x;         // < TBCN/4
    float4 xv = *(const float4*)(X + (size_t)idx * 4);
    float xin[4] = {xv.x, xv.y, xv.z, xv.w};
    __half t1[4], t2[4];
    #pragma unroll
    for (int j = 0; j < 4; j++) {
        t1[j] = __float2half_rn(xin[j]);
        t2[j] = __float2half_rn(xin[j] - __half2float(t1[j]));
    }
    *(uint2*)(g_xsplit[0] + (size_t)idx * 4) = *(uint2*)t1;
    *(uint2*)(g_xsplit[1] + (size_t)idx * 4) = *(uint2*)t2;
}

// ===========================================================================
// Pipelined WMMA projection GEMM + BN (fp32-accurate, fp16 3-term split).
// Pure streaming mainloop: W and X both pre-split in global, both
// double-buffered via cp.async, ONE sync per slab, no converts.
// One launch for q/k/v: blockIdx.z = tb*3 + proj.
// Block: 128(o) x 128(n); warp: 32(o) x 64(n); K in 8 slabs of 32.
// ===========================================================================
#define KS 32
#define NSLAB 8
#define LDW2 40                                    // 32 fp16 + 8 pad
#define LDX2 136                                   // 128 fp16 + 8 pad
#define WBUF_BYTES (2*128*LDW2*2)                  // 20480
#define XBUF_BYTES (2*KS*LDX2*2)                   // 17408
#define XS_OFF (2*WBUF_BYTES)                      // 40960
#define SMEM_GT (XS_OFF + 2*XBUF_BYTES)            // 75776 (stage 67584 unions at 0)

__global__ __launch_bounds__(256, 2)
void gemm_wmma_kernel(const float* __restrict__ qg, const float* __restrict__ qb,
                      const float* __restrict__ qm, const float* __restrict__ qv,
                      const float* __restrict__ kg, const float* __restrict__ kb,
                      const float* __restrict__ km, const float* __restrict__ kv,
                      const float* __restrict__ vg, const float* __restrict__ vb,
                      const float* __restrict__ vm, const float* __restrict__ vv)
{
    extern __shared__ __align__(16) char smem[];
    float* stage = (float*)smem;               // [128][132] (epilogue reuse)

    const int tid = threadIdx.x, wid = tid >> 5;
    const int n0 = blockIdx.x * 128;
    const int m0 = blockIdx.y * 128;
    const int proj = blockIdx.z % 3;
    const int tb = blockIdx.z / 3;
    float* Yb = g_y[proj] + (size_t)tb * CN_;

    const float* gamma = proj == 0 ? qg : (proj == 1 ? kg : vg);
    const float* beta  = proj == 0 ? qb : (proj == 1 ? kb : vb);
    const float* mean  = proj == 0 ? qm : (proj == 1 ? km : vm);
    const float* var   = proj == 0 ? qv : (proj == 1 ? kv : vv);
    const __half* W0 = g_wsplit[proj][0];
    const __half* W1 = g_wsplit[proj][1];
    const __half* X0 = g_xsplit[0] + (size_t)tb * CN_;
    const __half* X1 = g_xsplit[1] + (size_t)tb * CN_;

    const int wo = wid & 3;    // o-group (32 rows)
    const int wn = wid >> 2;   // n-group (64 cols)
    const uint32_t ws_base = smem_u32(smem);

    // per-thread cp.async coords
    // W: ch = p*256+tid < 1024: tm=ch>>9, r=(ch>>2)&127, v=ch&3
    // X: ch = p*256+tid < 1024: tm=ch>>9, r=(ch>>4)&31,  v=ch&15

    wmma::fragment<wmma::accumulator, 16, 16, 16, float> acc[2][4];
    #pragma unroll
    for (int i = 0; i < 2; i++)
        #pragma unroll
        for (int j = 0; j < 4; j++) wmma::fill_fragment(acc[i][j], 0.0f);

    // ---- prologue: slab 0 (W+X) into buf 0 ----
    #pragma unroll
    for (int p = 0; p < 4; p++) {
        int ch = p * 256 + tid;
        int tm = ch >> 9, r = (ch >> 2) & 127, v = ch & 3;
        cp_async16(ws_base + (uint32_t)((tm * 128 + r) * LDW2 * 2 + v * 16),
                   (tm ? W1 : W0) + (m0 + r) * 256 + v * 8);
    }
    #pragma unroll
    for (int p = 0; p < 4; p++) {
        int ch = p * 256 + tid;
        int tm = ch >> 9, r = (ch >> 4) & 31, v = ch & 15;
        cp_async16(ws_base + (uint32_t)(XS_OFF + (tm * KS + r) * LDX2 * 2 + v * 16),
                   (tm ? X1 : X0) + (size_t)r * N_ + n0 + v * 8);
    }
    asm volatile("cp.async.commit_group;");
    asm volatile("cp.async.wait_group 0;");
    __syncthreads();

    for (int s = 0; s < NSLAB; s++) {
        const int buf = s & 1;

        if (s < NSLAB - 1) {
            // slab s+1 (W+X) into alternate buffers (safe: last read at s-1)
            uint32_t wb = ws_base + (uint32_t)((buf ^ 1) * WBUF_BYTES);
            #pragma unroll
            for (int p = 0; p < 4; p++) {
                int ch = p * 256 + tid;
                int tm = ch >> 9, r = (ch >> 2) & 127, v = ch & 3;
                cp_async16(wb + (uint32_t)((tm * 128 + r) * LDW2 * 2 + v * 16),
                           (tm ? W1 : W0) + (m0 + r) * 256 + (s + 1) * KS + v * 8);
            }
            uint32_t xb = ws_base + (uint32_t)(XS_OFF + (buf ^ 1) * XBUF_BYTES);
            #pragma unroll
            for (int p = 0; p < 4; p++) {
                int ch = p * 256 + tid;
                int tm = ch >> 9, r = (ch >> 4) & 31, v = ch & 15;
                cp_async16(xb + (uint32_t)((tm * KS + r) * LDX2 * 2 + v * 16),
                           (tm ? X1 : X0) + (size_t)((s + 1) * KS + r) * N_ + n0 + v * 8);
            }
            asm volatile("cp.async.commit_group;");
        }

        // ---- MMA on slab s ----
        const __half* Wb = (const __half*)(smem + buf * WBUF_BYTES);
        const __half* Xs = (const __half*)(smem + XS_OFF + buf * XBUF_BYTES);
        #pragma unroll
        for (int ks = 0; ks < 2; ks++) {
            wmma::fragment<wmma::matrix_a, 16, 16, 16, __half, wmma::row_major> af[2][2];
            #pragma unroll
            for (int io = 0; io < 2; io++)
                #pragma unroll
                for (int tm = 0; tm < 2; tm++)
                    wmma::load_matrix_sync(af[io][tm],
                        Wb + tm * 128 * LDW2 + (wo * 32 + io * 16) * LDW2 + ks * 16, LDW2);
            #pragma unroll
            for (int jn = 0; jn < 4; jn++) {
                wmma::fragment<wmma::matrix_b, 16, 16, 16, __half, wmma::row_major> bf[2];
                #pragma unroll
                for (int tm = 0; tm < 2; tm++)
                    wmma::load_matrix_sync(bf[tm],
                        Xs + tm * KS * LDX2 + ks * 16 * LDX2 + wn * 64 + jn * 16, LDX2);
                #pragma unroll
                for (int io = 0; io < 2; io++) {
                    wmma::mma_sync(acc[io][jn], af[io][0], bf[0], acc[io][jn]);
                    wmma::mma_sync(acc[io][jn], af[io][1], bf[0], acc[io][jn]);
                    wmma::mma_sync(acc[io][jn], af[io][0], bf[1], acc[io][jn]);
                }
            }
        }

        if (s < NSLAB - 1)
            asm volatile("cp.async.wait_group 0;");
        __syncthreads();
    }

    // --- epilogue: frags -> smem stage, then BN + coalesced writes ---
    #pragma unroll
    for (int io = 0; io < 2; io++)
        #pragma unroll
        for (int jn = 0; jn < 4; jn++)
            wmma::store_matrix_sync(stage + (wo * 32 + io * 16) * 132 + wn * 64 + jn * 16,
                                    acc[io][jn], 132, wmma::mem_row_major);
    __syncthreads();

    #pragma unroll
    for (int p = 0; p < 16; p++) {
        int idx = p * 256 + tid;
        int row = idx >> 5, c4 = (idx & 31) * 4;
        int o = m0 + row;
        float sc = gamma[o] * rsqrtf(var[o] + 1e-5f);
        float sh = beta[o] - mean[o] * sc;
        const float* sp = stage + row * 132 + c4;
        float4 yv = make_float4(sp[0] * sc + sh, sp[1] * sc + sh,
                                sp[2] * sc + sh, sp[3] * sc + sh);
        *(float4*)(Yb + (size_t)o * N_ + n0 + c4) = yv;
    }
}

// ===========================================================================
// LIF over T (vth=1) + bitpack for q,k,v. One thread per (b,h,n);
// d-loop unrolled x2 -> 8 independent loads in flight (latency hiding).
// ===========================================================================
__global__ __launch_bounds__(256)
void lif_pack_kernel()
{
    const int proj = blockIdx.y;
    const int idx = blockIdx.x * 256 + threadIdx.x;  // < B*8*N = 131072
    const int n = idx & (N_ - 1);
    const int h = (idx >> 10) & 7;
    const int b = idx >> 13;
    const float* Y = g_y[proj];
    const float* base = Y + (size_t)b * CN_ + (size_t)(h * 32) * N_ + n;

    unsigned bits[4] = {0u, 0u, 0u, 0u};
    for (int d = 0; d < 32; d += 2) {
        const float* p0 = base + (size_t)d * N_;
        const float* p1 = p0 + N_;
        float m0 = 0.f, m1 = 0.f;
        #pragma unroll
        for (int t = 0; t < 4; t++) {
            float y0 = p0[(size_t)t * BCN];
            float y1 = p1[(size_t)t * BCN];
            m0 += (y0 - m0) * 0.5f;
            m1 += (y1 - m1) * 0.5f;
            if (m0 >= 1.0f) { bits[t] |= (1u << d); m0 = 0.f; }
            if (m1 >= 1.0f) { bits[t] |= (2u << d); m1 = 0.f; }
        }
    }
    const int ob = (b * 8 + h) * N_ + n;
    #pragma unroll
    for (int t = 0; t < 4; t++)
        g_bits[proj][t * BHN + ob] = bits[t];
}

// ===========================================================================
// v output: 4 consecutive bits of one word -> one float4; fully coalesced.
// ===========================================================================
__global__ __launch_bounds__(256)
void v_writer_kernel(float4* __restrict__ vout)
{
    const int idx = blockIdx.x * 256 + threadIdx.x;   // < TBCN/4
    unsigned w = g_bits[2][idx >> 3];
    int sh = (idx & 7) * 4;
    vout[idx] = make_float4((float)((w >> sh) & 1u), (float)((w >> (sh + 1)) & 1u),
                            (float)((w >> (sh + 2)) & 1u), (float)((w >> (sh + 3)) & 1u));
}

// ===========================================================================
// Per (t,b,h): kv[d][e] = popc over n of k_d & v_e -> g_kvm (2 MB).
// ===========================================================================
__global__ __launch_bounds__(256)
void kv_only_kernel()
{
    __shared__ unsigned kb[1024], vb[1024];
    __shared__ unsigned krow[32][33], vrow[32][33];

    const int bid = blockIdx.x;    // (t*B+b)*8+h
    const int tid = threadIdx.x;
    const unsigned base = (unsigned)bid * 1024u;

    for (int i = tid; i < 1024; i += 256) {
        kb[i] = g_bits[1][base + i];
        vb[i] = g_bits[2][base + i];
    }
    __syncthreads();

    const int d = tid & 31;
    for (int w = tid >> 5; w < 32; w += 8) {
        unsigned rk = 0u, rv = 0u;
        #pragma unroll
        for (int j = 0; j < 32; j++) {
            rk |= ((kb[w * 32 + j] >> d) & 1u) << j;
            rv |= ((vb[w * 32 + j] >> d) & 1u) << j;
        }
        krow[d][w] = rk; vrow[d][w] = rv;
    }
    __syncthreads();

    for (int p = tid; p < 1024; p += 256) {
        int dd = p >> 5, e = p & 31;
        int s = 0;
        #pragma unroll
        for (int w = 0; w < 32; w++)
            s += __popc(krow[dd][w] & vrow[e][w]);
        g_kvm[base + p] = (float)s;
    }
}

// ===========================================================================
// attn-apply + LIF(0.5) + xs bitpack (no g_xa).
// ===========================================================================
__global__ __launch_bounds__(256)
void attn_lif_kernel()
{
    __shared__ float kvm[4][32][33];

    const int n0 = blockIdx.x * 256;
    const int h  = blockIdx.y;
    const int b  = blockIdx.z;
    const int tid = threadIdx.x;

    for (int i = tid; i < 4096; i += 256) {
        int t = i >> 10, p = i & 1023;
        kvm[t][p >> 5][p & 31] = g_kvm[(size_t)((t * B_ + b) * 8 + h) * 1024 + p];
    }
    __syncthreads();

    float mem[32];
    #pragma unroll
    for (int e = 0; e < 32; e++) mem[e] = 0.f;

    const int ob = (b * 8 + h) * N_ + n0 + tid;
    #pragma unroll
    for (int t = 0; t < 4; t++) {
        unsigned qm = g_bits[0][t * BHN + ob];
        unsigned bitsout = 0u;
        if (qm) {
            #pragma unroll
            for (int e = 0; e < 32; e++) {
                float s = 0.f;
                #pragma unroll
                for (int d = 0; d < 32; d++)
                    if (qm & (1u << d)) s += kvm[t][d][e];
                float y = 0.125f * s;
                mem[e] += (y - mem[e]) * 0.5f;
                if (mem[e] >= 0.5f) { bitsout |= (1u << e); mem[e] = 0.f; }
            }
        } else {
            #pragma unroll
            for (int e = 0; e < 32; e++) mem[e] *= 0.5f;
        }
        g_bits[3][t * BHN + ob] = bitsout;
    }
}

__global__ __launch_bounds__(256)
void wt_kernel(const float* __restrict__ pw)
{
    int idx = blockIdx.x * 256 + threadIdx.x;
    int o = idx & 255, c = idx >> 8;
    g_wt[c * 256 + o] = pw[o * 256 + c];
}

// ===========================================================================
// Fused sparse p-GEMM + bias + BN + LIF(1.0) -> out.
// og loop split over grid.y (4x blocks vs R13) for occupancy.
// ===========================================================================
__global__ __launch_bounds__(256)
void sparse_p_out_kernel(const float* __restrict__ pb,
                         const float* __restrict__ pg,
                         const float* __restrict__ pbt,
                         const float* __restrict__ pm,
                         const float* __restrict__ pv,
                         float* __restrict__ out)
{
    __shared__ unsigned mw[4][8][64];
    __shared__ unsigned fl[4][64];
    __shared__ float s_sc[256], s_sh[256], s_bi[256];

    const int n0 = blockIdx.x * 64;
    const int ogb = blockIdx.y;          // 0..3
    const int b  = blockIdx.z;
    const int tid = threadIdx.x;

    {
        float sc = pg[tid] * rsqrtf(pv[tid] + 1e-5f);
        s_sc[tid] = sc;
        s_sh[tid] = pbt[tid] - pm[tid] * sc;
        s_bi[tid] = pb[tid];
    }
    for (int i = tid; i < 2048; i += 256) {
        int nn = i & 63, w = (i >> 6) & 7, t = i >> 9;
        mw[t][w][nn] = g_bits[3][t * BHN + (b * 8 + w) * N_ + n0 + nn];
    }
    __syncthreads();
    {
        int t = tid >> 6, nn = tid & 63;
        unsigned f = 0;
        #pragma unroll
        for (int w = 0; w < 8; w++) f |= mw[t][w][nn];
        fl[t][nn] = f;
    }
    __syncthreads();

    const int wi = tid >> 5, lane = tid & 31;
    for (int og = 0; og < 8; og++) {
        int o = (ogb * 8 + og) * 8 + wi;
        float sc = s_sc[o], sh = s_sh[o], bi = s_bi[o];
        float v0 = bi * sc + sh;
        #pragma unroll
        for (int nn2 = 0; nn2 < 2; nn2++) {
            int nn = nn2 * 32 + lane;
            float mem = 0.f;
            #pragma unroll
            for (int t = 0; t < 4; t++) {
                float y = v0;
                if (fl[t][nn]) {
                    float acc = 0.f;
                    #pragma unroll 1
                    for (int w = 0; w < 8; w++) {
                        unsigned m = mw[t][w][nn];
                        while (m) {
                            int d = __ffs(m) - 1;
                            m &= m - 1;
                            acc += g_wt[(w * 32 + d) * 256 + o];
                        }
                    }
                    y = (acc + bi) * sc + sh;
                }
                mem += (y - mem) * 0.5f;
                float s = (mem >= 1.0f) ? 1.0f : 0.0f;
                out[(size_t)t * BCN + (size_t)b * CN_ + (size_t)o * N_ + n0 + nn] = s;
                mem *= (1.0f - s);
            }
        }
    }
}

// ===========================================================================
extern "C" void kernel_launch(void* const* d_in, const int* in_sizes, int n_in,
                              void* d_out, int out_size)
{
    const float* x  = (const float*)d_in[0];
    const float* qw = (const float*)d_in[2];
    const float* qg = (const float*)d_in[3];
    const float* qb = (const float*)d_in[4];
    const float* qm = (const float*)d_in[5];
    const float* qv = (const float*)d_in[6];
    const float* kw = (const float*)d_in[7];
    const float* kg = (const float*)d_in[8];
    const float* kb = (const float*)d_in[9];
    const float* km = (const float*)d_in[10];
    const float* kv = (const float*)d_in[11];
    const float* vw = (const float*)d_in[12];
    const float* vg = (const float*)d_in[13];
    const float* vb = (const float*)d_in[14];
    const float* vm = (const float*)d_in[15];
    const float* vv = (const float*)d_in[16];
    const float* pw = (const float*)d_in[17];
    const float* pb = (const float*)d_in[18];
    const float* pg = (const float*)d_in[19];
    const float* pbt = (const float*)d_in[20];
    const float* pm = (const float*)d_in[21];
    const float* pv = (const float*)d_in[22];

    float* out  = (float*)d_out;
    float* vout = (out_size >= 2 * TBCN) ? out + TBCN : nullptr;

    static int smem_set = 0;
    if (!smem_set) {
        cudaFuncSetAttribute(gemm_wmma_kernel,
                             cudaFuncAttributeMaxDynamicSharedMemorySize, SMEM_GT);
        smem_set = 1;
    }

    // one-shot preps: W split, X split, p_w transpose
    wsplit_kernel<<<3 * C_ * C_ / 256, 256>>>(qw, kw, vw);
    xsplit_kernel<<<TBCN / 1024, 256>>>(x);
    wt_kernel<<<C_ * C_ / 256, 256>>>(pw);

    // q,k,v projections: pure-streaming pipelined wmma (fp16 3-term)
    dim3 tgrid(N_ / 128, C_ / 128, T_ * B_ * 3);
    gemm_wmma_kernel<<<tgrid, 256, SMEM_GT>>>(qg, qb, qm, qv,
                                              kg, kb, km, kv, vg, vb, vm, vv);

    // LIF(1.0) + bitpack for q,k,v
    lif_pack_kernel<<<dim3(BHN / 256, 3), 256>>>();

    // v output (coalesced float4)
    if (vout)
        v_writer_kernel<<<TBCN / 1024, 256>>>((float4*)vout);

    // kv matrices -> g_kvm
    kv_only_kernel<<<T_ * B_ * 8, 256>>>();

    // attn-apply + LIF(0.5) + xs bitpack
    attn_lif_kernel<<<dim3(N_ / 256, 8, B_), 256>>>();

    // fused sparse p-GEMM + BN + LIF(1.0) -> out
    sparse_p_out_kernel<<<dim3(N_ / 64, 4, B_), 256>>>(pb, pg, pbt, pm, pv, out);
}